// round 14
// baseline (speedup 1.0000x reference)
#include <cuda_runtime.h>
#include <cuda_fp16.h>
#include <cstdint>

// ---------------------------------------------------------------------------
// Problem constants
// ---------------------------------------------------------------------------
#define T_STEPS 2048
#define BATCH   64
#define INSZ    512
#define HID     256
#define G4      1024      // 4*HID
#define OUTSZ   128
#define MROWS   (T_STEPS * BATCH)   // 131072

// Scratch (device globals: allocation-free per harness rules)
__device__ float g_Xp[(size_t)MROWS * G4];                 // input projection
__device__ uint4 g_Ah[(size_t)MROWS * INSZ / 4];           // inputs, fp16 hi/lo split
__device__ uint4 g_Wih[(size_t)G4 * INSZ / 4];             // W_ih split
__device__ uint4 g_hsh[(size_t)MROWS * HID / 4];           // hs, split (written by rec)
__device__ uint4 g_Wfc[(size_t)OUTSZ * HID / 4];           // W_fc split

// ---------------------------------------------------------------------------
// Helpers
// ---------------------------------------------------------------------------
__device__ __forceinline__ void ffma2(float2& d, const float2& a, const float2& b)
{
    asm("fma.rn.f32x2 %0, %1, %2, %0;"
        : "+l"(reinterpret_cast<unsigned long long&>(d))
        : "l"(reinterpret_cast<const unsigned long long&>(a)),
          "l"(reinterpret_cast<const unsigned long long&>(b)));
}

__device__ __forceinline__ float tanh_ap(float x)
{
    float y;
    asm("tanh.approx.f32 %0, %1;" : "=f"(y) : "f"(x));
    return y;
}
__device__ __forceinline__ float sig_ap(float x)
{
    return fmaf(tanh_ap(0.5f * x), 0.5f, 0.5f);
}

__device__ __forceinline__ uint2 split_h2(float x, float y)
{
    __half2 hi = __floats2half2_rn(x, y);
    float2 hf = __half22float2(hi);
    __half2 lo = __floats2half2_rn(x - hf.x, y - hf.y);
    uint2 r;
    r.x = *(uint32_t*)&hi;
    r.y = *(uint32_t*)&lo;
    return r;
}

__device__ __forceinline__ void mbar_init(uint32_t addr, uint32_t count)
{
    asm volatile("mbarrier.init.shared.b64 [%0], %1;" :: "r"(addr), "r"(count)
                 : "memory");
}
__device__ __forceinline__ void mbar_expect_tx(uint32_t addr, uint32_t bytes)
{
    asm volatile("mbarrier.arrive.expect_tx.shared.b64 _, [%0], %1;"
                 :: "r"(addr), "r"(bytes) : "memory");
}
__device__ __forceinline__ void mbar_wait(uint32_t addr, uint32_t parity)
{
    asm volatile(
        "{\n\t"
        ".reg .pred P;\n\t"
        "LW%=:\n\t"
        "mbarrier.try_wait.parity.acquire.cta.shared::cta.b64 P, [%0], %1;\n\t"
        "@P bra LD%=;\n\t"
        "bra LW%=;\n\t"
        "LD%=:\n\t"
        "}"
        :: "r"(addr), "r"(parity) : "memory");
}

__device__ __forceinline__ void cp16(uint32_t dst, const void* src)
{
    asm volatile("cp.async.cg.shared.global [%0], [%1], 16;"
                 :: "r"(dst), "l"(src) : "memory");
}
__device__ __forceinline__ void cp_commit()
{
    asm volatile("cp.async.commit_group;" ::: "memory");
}

__device__ __forceinline__ void nbar_sync(int id)
{
    asm volatile("bar.sync %0, 256;" :: "r"(id) : "memory");
}
__device__ __forceinline__ void nbar_arrive(int id)
{
    asm volatile("bar.arrive %0, 256;" :: "r"(id) : "memory");
}

// ---------------------------------------------------------------------------
// Pre-split: fp32 -> (hi fp16, lo fp16) packed as uint2 per fp32-pair.
// ---------------------------------------------------------------------------
__global__ void presplit(const float4* __restrict__ in, uint4* __restrict__ out,
                         int n4)
{
    for (int i = blockIdx.x * blockDim.x + threadIdx.x; i < n4;
         i += gridDim.x * blockDim.x) {
        float4 v = in[i];
        uint2 a = split_h2(v.x, v.y);
        uint2 b = split_h2(v.z, v.w);
        out[i] = make_uint4(a.x, a.y, b.x, b.y);
    }
}

// ---------------------------------------------------------------------------
// 3-term fp16 split GEMM (NT), PRE-SPLIT operands, 2-stage cp.async pipeline
// (R11 measured-best version, unchanged).
// ---------------------------------------------------------------------------
#define MMA_F16(d, a0, a1, a2, a3, b0, b1)                                    \
    asm("mma.sync.aligned.m16n8k16.row.col.f32.f16.f16.f32 "                   \
        "{%0,%1,%2,%3},{%4,%5,%6,%7},{%8,%9},{%0,%1,%2,%3};"                   \
        : "+f"((d)[0]), "+f"((d)[1]), "+f"((d)[2]), "+f"((d)[3])               \
        : "r"(a0), "r"(a1), "r"(a2), "r"(a3), "r"(b0), "r"(b1))

#define HPAD 10   // uint2 row stride (8 kpairs + 2 pad)

__global__ void __launch_bounds__(256, 2)
hgemm_pre(const uint2* __restrict__ Ah, const uint2* __restrict__ Bh,
          const float* __restrict__ bias1, const float* __restrict__ bias2,
          float* __restrict__ C, int K2, int N)
{
    __shared__ uint2 As[2][128][HPAD];
    __shared__ uint2 Bs[2][128][HPAD];

    const int tid  = threadIdx.x;
    const int lane = tid & 31;
    const int warp = tid >> 5;
    const int wm = warp & 1;
    const int wn = warp >> 1;
    const int g  = lane >> 2;
    const int t  = lane & 3;

    const size_t m0 = (size_t)blockIdx.x * 128;
    const int    n0 = blockIdx.y * 128;

    const int frow = tid >> 1;
    const int fc2  = (tid & 1) * 4;
    const uint2* Ag = Ah + (m0 + frow) * (size_t)K2 + fc2;
    const uint2* Bg = Bh + (size_t)(n0 + frow) * K2 + fc2;

    const uint32_t sA0 = (uint32_t)__cvta_generic_to_shared(&As[0][frow][fc2]);
    const uint32_t sA1 = (uint32_t)__cvta_generic_to_shared(&As[1][frow][fc2]);
    const uint32_t sB0 = (uint32_t)__cvta_generic_to_shared(&Bs[0][frow][fc2]);
    const uint32_t sB1 = (uint32_t)__cvta_generic_to_shared(&Bs[1][frow][fc2]);

    const int nblk = K2 >> 3;

    cp16(sA0, Ag);          cp16(sA0 + 16, Ag + 2);
    cp16(sB0, Bg);          cp16(sB0 + 16, Bg + 2);
    cp_commit();
    cp16(sA1, Ag + 8);      cp16(sA1 + 16, Ag + 10);
    cp16(sB1, Bg + 8);      cp16(sB1 + 16, Bg + 10);
    cp_commit();

    float acc[4][4][4];
#pragma unroll
    for (int i = 0; i < 4; ++i)
#pragma unroll
        for (int j = 0; j < 4; ++j)
#pragma unroll
            for (int q = 0; q < 4; ++q) acc[i][j][q] = 0.f;

    for (int kb = 0; kb < nblk; ++kb) {
        if (kb == nblk - 1)
            asm volatile("cp.async.wait_group 0;" ::: "memory");
        else
            asm volatile("cp.async.wait_group 1;" ::: "memory");
        __syncthreads();

        const int s = kb & 1;
        uint32_t ah[4][4], al[4][4], bh[4][2], bl[4][2];
#pragma unroll
        for (int i = 0; i < 4; ++i) {
            const int row = wm * 64 + i * 16 + g;
            uint2 q00 = As[s][row][t];
            uint2 q10 = As[s][row + 8][t];
            uint2 q01 = As[s][row][t + 4];
            uint2 q11 = As[s][row + 8][t + 4];
            ah[i][0] = q00.x; ah[i][1] = q10.x; ah[i][2] = q01.x; ah[i][3] = q11.x;
            al[i][0] = q00.y; al[i][1] = q10.y; al[i][2] = q01.y; al[i][3] = q11.y;
        }
#pragma unroll
        for (int j = 0; j < 4; ++j) {
            const int n = wn * 32 + j * 8 + g;
            uint2 p0 = Bs[s][n][t];
            uint2 p1 = Bs[s][n][t + 4];
            bh[j][0] = p0.x; bh[j][1] = p1.x;
            bl[j][0] = p0.y; bl[j][1] = p1.y;
        }
#pragma unroll
        for (int i = 0; i < 4; ++i)
#pragma unroll
            for (int j = 0; j < 4; ++j) {
                MMA_F16(acc[i][j], ah[i][0], ah[i][1], ah[i][2], ah[i][3],
                        bh[j][0], bh[j][1]);
                MMA_F16(acc[i][j], ah[i][0], ah[i][1], ah[i][2], ah[i][3],
                        bl[j][0], bl[j][1]);
                MMA_F16(acc[i][j], al[i][0], al[i][1], al[i][2], al[i][3],
                        bh[j][0], bh[j][1]);
            }
        __syncthreads();

        if (kb + 2 < nblk) {
            const int koff = (kb + 2) * 8;
            cp16(s ? sA1 : sA0, Ag + koff);
            cp16((s ? sA1 : sA0) + 16, Ag + koff + 2);
            cp16(s ? sB1 : sB0, Bg + koff);
            cp16((s ? sB1 : sB0) + 16, Bg + koff + 2);
            cp_commit();
        }
    }

#pragma unroll
    for (int j = 0; j < 4; ++j) {
        int col = n0 + wn * 32 + j * 8 + 2 * t;
        float b0 = bias1[col], b1 = bias1[col + 1];
        if (bias2) { b0 += bias2[col]; b1 += bias2[col + 1]; }
#pragma unroll
        for (int i = 0; i < 4; ++i) {
            size_t row = m0 + wm * 64 + i * 16 + g;
            *(float2*)(C + row * N + col) =
                make_float2(acc[i][j][0] + b0, acc[i][j][1] + b1);
            *(float2*)(C + (row + 8) * N + col) =
                make_float2(acc[i][j][2] + b0, acc[i][j][3] + b1);
        }
    }
}

// ---------------------------------------------------------------------------
// LSTM recurrence v8: two-group pipeline, producer/consumer named barriers
// with ALTERNATING IDS (A: 1/2, B: 3/4 by t parity) and DOUBLE-BUFFERED
// partials part[g][t&1].
//
// Soundness:
//  * Barrier ID reuse: a warp re-arriving on ID (1 + (t&1)) at t+2 must pass
//    waitA(t+2) <= rank-w reducer synced at t+1 <= its warp r passed
//    waitA(t+1) <= OUR scatter at t <= our reducers tripped phase t of that
//    ID. So no warp arrives twice in one phase.
//  * WAR on part[g][ph]: earliest rewrite is t+2; same chain shows our
//    reducers finished reading it at t.
//  * mbar re-arm after bar.sync: all local warps passed their waits (they
//    arrived at the barrier after their wait this step).
// Gates use tanh.approx.f32 (MUFU.TANH).
// ---------------------------------------------------------------------------
__global__ void __launch_bounds__(256, 1)
lstm_rec_kernel(const float* __restrict__ Whh,
                const float* __restrict__ Xp,
                uint2* __restrict__ hs_h)
{
    __shared__ float  hsm[2][3][8][64];        // [g][slot][rank][bb*32+jj]
    __shared__ float4 part[2][2][8][2][32];    // [g][ph][warp][bb][jj]
    __shared__ __align__(8) unsigned long long mbar[48];  // [g][slot][rank]

    const int tid  = threadIdx.x;
    const int lane = tid & 31;
    const int w    = tid >> 5;

    unsigned r;
    asm("mov.u32 %0, %%cluster_ctarank;" : "=r"(r));
    const int cl = blockIdx.x >> 3;

    const uint32_t hsm_s = (uint32_t)__cvta_generic_to_shared(hsm);
    const uint32_t mb_s  = (uint32_t)__cvta_generic_to_shared(mbar);

    uint32_t pd[8], pm[8];
#pragma unroll
    for (int dst = 0; dst < 8; ++dst) {
        asm("mapa.shared::cluster.u32 %0, %1, %2;"
            : "=r"(pd[dst]) : "r"(hsm_s), "r"(dst));
        asm("mapa.shared::cluster.u32 %0, %1, %2;"
            : "=r"(pm[dst]) : "r"(mb_s), "r"(dst));
    }

    float2 wreg[4][16];
#pragma unroll
    for (int rr = 0; rr < 4; ++rr) {
        int grow = rr * 256 + (int)r * 32 + lane;
        const float2* wp = (const float2*)(Whh + (size_t)grow * 256 + w * 32);
#pragma unroll
        for (int k2 = 0; k2 < 16; ++k2) wreg[rr][k2] = wp[k2];
    }
    for (int i = tid; i < 2 * 3 * 8 * 64; i += 256) ((float*)hsm)[i] = 0.f;
    if (tid < 48) mbar_init(mb_s + tid * 8, 1);
    __syncthreads();
    if (tid < 48) mbar_expect_tx(mb_s + tid * 8, 256u);
    asm volatile("barrier.cluster.arrive.aligned;" ::: "memory");
    asm volatile("barrier.cluster.wait.aligned;"   ::: "memory");

    const int mg = tid >> 6;           // reducer group (tid<128)
    const int tl = tid & 63;
    const int bb = tl >> 5;
    const int jj = tl & 31;
    float c = 0.f;
    int par = 0;
    int rs = 0;

    const float* xp_base = Xp + ((size_t)cl * 4 + mg * 2 + bb) * 1024
                              + (int)r * 32 + jj;
    float xc0 = 0.f, xc1 = 0.f, xc2 = 0.f, xc3 = 0.f;
    if (tid < 128) {
        xc0 = xp_base[0]; xc1 = xp_base[256];
        xc2 = xp_base[512]; xc3 = xp_base[768];
    }

    for (int t = 0; t < T_STEPS; ++t) {
        const int ws = (rs == 2) ? 0 : rs + 1;
        const int ph = t & 1;

        // ================= group A =================
        if (t > 0)
            mbar_wait(mb_s + ((0 * 3 + rs) * 8 + w) * 8, (par >> rs) & 1);

        float xn0 = 0.f, xn1 = 0.f, xn2 = 0.f, xn3 = 0.f;
        if (tid < 128 && t + 1 < T_STEPS) {
            const float* xp = xp_base + (size_t)(t + 1) * 64 * 1024;
            xn0 = xp[0]; xn1 = xp[256]; xn2 = xp[512]; xn3 = xp[768];
        }

        {   // dot A (all 8 warps) -> part[0][ph]
            float2 acc[4][2];
#pragma unroll
            for (int rr = 0; rr < 4; ++rr) {
                acc[rr][0] = make_float2(0.f, 0.f);
                acc[rr][1] = make_float2(0.f, 0.f);
            }
            const float* hb = &hsm[0][rs][w][0];
#pragma unroll
            for (int k2 = 0; k2 < 16; ++k2) {
                float2 h0 = *(const float2*)(hb + 2 * k2);
                float2 h1 = *(const float2*)(hb + 32 + 2 * k2);
#pragma unroll
                for (int rr = 0; rr < 4; ++rr) {
                    ffma2(acc[rr][0], wreg[rr][k2], h0);
                    ffma2(acc[rr][1], wreg[rr][k2], h1);
                }
            }
#pragma unroll
            for (int b = 0; b < 2; ++b)
                part[0][ph][w][b][lane] =
                    make_float4(acc[0][b].x + acc[0][b].y,
                                acc[1][b].x + acc[1][b].y,
                                acc[2][b].x + acc[2][b].y,
                                acc[3][b].x + acc[3][b].y);
        }
        if (w < 2) nbar_sync(1 + ph);
        else       nbar_arrive(1 + ph);

        if (tid < 64) {
            if (t > 0 && tid < 8)
                mbar_expect_tx(mb_s + ((0 * 3 + rs) * 8 + tid) * 8, 256u);

            float s0 = xc0, s1 = xc1, s2 = xc2, s3 = xc3;
#pragma unroll
            for (int w8 = 0; w8 < 8; ++w8) {
                float4 p = part[0][ph][w8][bb][jj];
                s0 += p.x; s1 += p.y; s2 += p.z; s3 += p.w;
            }
            float ig = sig_ap(s0);
            float fg = sig_ap(s1);
            float gg = tanh_ap(s2);
            float og = sig_ap(s3);
            c = fg * c + ig * gg;
            float h = og * tanh_ap(c);

            if (t < T_STEPS - 1) {
                uint32_t hv = __float_as_uint(h);
                uint32_t doff = (uint32_t)(ws * 2048 + (int)r * 256 + tl * 4);
                uint32_t moff = (uint32_t)(((0 * 3 + ws) * 8 + (int)r) * 8);
#pragma unroll
                for (int dst = 0; dst < 8; ++dst)
                    asm volatile(
                        "st.async.shared::cluster.mbarrier::complete_tx::bytes"
                        ".u32 [%0], %1, [%2];"
                        :: "r"(pd[dst] + doff), "r"(hv), "r"(pm[dst] + moff)
                        : "memory");
            }
            float hn = __shfl_down_sync(0xFFFFFFFFu, h, 1);
            if (!(jj & 1)) {
                uint2 sv = split_h2(h, hn);
                hs_h[((size_t)t * 64 + cl * 4 + bb) * 128
                     + (int)r * 16 + (jj >> 1)] = sv;
            }
        }

        // ================= group B =================
        if (t > 0)
            mbar_wait(mb_s + ((1 * 3 + rs) * 8 + w) * 8, (par >> rs) & 1);

        {   // dot B (all 8 warps) -> part[1][ph]
            float2 acc[4][2];
#pragma unroll
            for (int rr = 0; rr < 4; ++rr) {
                acc[rr][0] = make_float2(0.f, 0.f);
                acc[rr][1] = make_float2(0.f, 0.f);
            }
            const float* hb = &hsm[1][rs][w][0];
#pragma unroll
            for (int k2 = 0; k2 < 16; ++k2) {
                float2 h0 = *(const float2*)(hb + 2 * k2);
                float2 h1 = *(const float2*)(hb + 32 + 2 * k2);
#pragma unroll
                for (int rr = 0; rr < 4; ++rr) {
                    ffma2(acc[rr][0], wreg[rr][k2], h0);
                    ffma2(acc[rr][1], wreg[rr][k2], h1);
                }
            }
#pragma unroll
            for (int b = 0; b < 2; ++b)
                part[1][ph][w][b][lane] =
                    make_float4(acc[0][b].x + acc[0][b].y,
                                acc[1][b].x + acc[1][b].y,
                                acc[2][b].x + acc[2][b].y,
                                acc[3][b].x + acc[3][b].y);
        }
        if (w == 2 || w == 3) nbar_sync(3 + ph);
        else                  nbar_arrive(3 + ph);

        if (tid >= 64 && tid < 128) {
            if (t > 0 && tid < 72)
                mbar_expect_tx(mb_s + ((1 * 3 + rs) * 8 + (tid - 64)) * 8, 256u);

            float s0 = xc0, s1 = xc1, s2 = xc2, s3 = xc3;
#pragma unroll
            for (int w8 = 0; w8 < 8; ++w8) {
                float4 p = part[1][ph][w8][bb][jj];
                s0 += p.x; s1 += p.y; s2 += p.z; s3 += p.w;
            }
            float ig = sig_ap(s0);
            float fg = sig_ap(s1);
            float gg = tanh_ap(s2);
            float og = sig_ap(s3);
            c = fg * c + ig * gg;
            float h = og * tanh_ap(c);

            if (t < T_STEPS - 1) {
                uint32_t hv = __float_as_uint(h);
                uint32_t doff = (uint32_t)(6144 + ws * 2048 + (int)r * 256
                                           + tl * 4);
                uint32_t moff = (uint32_t)(((1 * 3 + ws) * 8 + (int)r) * 8);
#pragma unroll
                for (int dst = 0; dst < 8; ++dst)
                    asm volatile(
                        "st.async.shared::cluster.mbarrier::complete_tx::bytes"
                        ".u32 [%0], %1, [%2];"
                        :: "r"(pd[dst] + doff), "r"(hv), "r"(pm[dst] + moff)
                        : "memory");
            }
            float hn = __shfl_down_sync(0xFFFFFFFFu, h, 1);
            if (!(jj & 1)) {
                uint2 sv = split_h2(h, hn);
                hs_h[((size_t)t * 64 + cl * 4 + 2 + bb) * 128
                     + (int)r * 16 + (jj >> 1)] = sv;
            }
        }

        xc0 = xn0; xc1 = xn1; xc2 = xn2; xc3 = xn3;
        if (t > 0) par ^= (1 << rs);
        rs = ws;
    }

    asm volatile("barrier.cluster.arrive.aligned;" ::: "memory");
    asm volatile("barrier.cluster.wait.aligned;"   ::: "memory");
}

// ---------------------------------------------------------------------------
// Launch
// ---------------------------------------------------------------------------
extern "C" void kernel_launch(void* const* d_in, const int* in_sizes, int n_in,
                              void* d_out, int out_size)
{
    const float* inputs = (const float*)d_in[0];
    const float* W_ih   = (const float*)d_in[1];
    const float* W_hh   = (const float*)d_in[2];
    const float* b_ih   = (const float*)d_in[3];
    const float* b_hh   = (const float*)d_in[4];
    const float* W_fc   = (const float*)d_in[5];
    const float* b_fc   = (const float*)d_in[6];
    float* out = (float*)d_out;

    float *Xp;
    uint4 *Ah, *Wih, *hsh, *Wfc;
    cudaGetSymbolAddress((void**)&Xp,  g_Xp);
    cudaGetSymbolAddress((void**)&Ah,  g_Ah);
    cudaGetSymbolAddress((void**)&Wih, g_Wih);
    cudaGetSymbolAddress((void**)&hsh, g_hsh);
    cudaGetSymbolAddress((void**)&Wfc, g_Wfc);

    // 0) Pre-split fp32 -> fp16 hi/lo pairs.
    presplit<<<4096, 256>>>((const float4*)inputs, Ah, MROWS * INSZ / 4);
    presplit<<<512, 256>>>((const float4*)W_ih, Wih, G4 * INSZ / 4);
    presplit<<<32, 256>>>((const float4*)W_fc, Wfc, OUTSZ * HID / 4);

    // 1) Xp = inputs @ W_ih^T + (b_ih + b_hh)   [131072 x 1024]
    {
        dim3 grid(MROWS / 128, G4 / 128);
        hgemm_pre<<<grid, 256>>>((const uint2*)Ah, (const uint2*)Wih,
                                 b_ih, b_hh, Xp, INSZ / 2, G4);
    }

    // 2) LSTM recurrence -> hs (pre-split) [131072 x 256]
    {
        cudaLaunchConfig_t cfg = {};
        cfg.gridDim = dim3(128, 1, 1);
        cfg.blockDim = dim3(256, 1, 1);
        cfg.dynamicSmemBytes = 0;
        cfg.stream = 0;
        cudaLaunchAttribute attr[1];
        attr[0].id = cudaLaunchAttributeClusterDimension;
        attr[0].val.clusterDim.x = 8;
        attr[0].val.clusterDim.y = 1;
        attr[0].val.clusterDim.z = 1;
        cfg.attrs = attr;
        cfg.numAttrs = 1;
        cudaLaunchKernelEx(&cfg, lstm_rec_kernel, W_hh, (const float*)Xp,
                           (uint2*)hsh);
    }

    // 3) out = hs @ W_fc^T + b_fc   [131072 x 128]
    {
        dim3 grid(MROWS / 128, OUTSZ / 128);
        hgemm_pre<<<grid, 256>>>((const uint2*)hsh, (const uint2*)Wfc,
                                 b_fc, (const float*)nullptr, out,
                                 HID / 2, OUTSZ);
    }
}

// round 15
// speedup vs baseline: 1.1098x; 1.1098x over previous
#include <cuda_runtime.h>
#include <cuda_fp16.h>
#include <cstdint>

// ---------------------------------------------------------------------------
// Problem constants
// ---------------------------------------------------------------------------
#define T_STEPS 2048
#define BATCH   64
#define INSZ    512
#define HID     256
#define G4      1024      // 4*HID
#define OUTSZ   128
#define MROWS   (T_STEPS * BATCH)   // 131072

// Scratch (device globals: allocation-free per harness rules)
__device__ float g_Xp[(size_t)MROWS * G4];                 // input projection
__device__ uint4 g_Ah[(size_t)MROWS * INSZ / 4];           // inputs, fp16 hi/lo split
__device__ uint4 g_Wih[(size_t)G4 * INSZ / 4];             // W_ih split
__device__ uint4 g_hsh[(size_t)MROWS * HID / 4];           // hs, split (written by rec)
__device__ uint4 g_Wfc[(size_t)OUTSZ * HID / 4];           // W_fc split

// ---------------------------------------------------------------------------
// Helpers
// ---------------------------------------------------------------------------
__device__ __forceinline__ void ffma2(float2& d, const float2& a, const float2& b)
{
    asm("fma.rn.f32x2 %0, %1, %2, %0;"
        : "+l"(reinterpret_cast<unsigned long long&>(d))
        : "l"(reinterpret_cast<const unsigned long long&>(a)),
          "l"(reinterpret_cast<const unsigned long long&>(b)));
}

__device__ __forceinline__ float tanh_ap(float x)
{
    float y;
    asm("tanh.approx.f32 %0, %1;" : "=f"(y) : "f"(x));
    return y;
}
__device__ __forceinline__ float sig_ap(float x)
{
    return fmaf(tanh_ap(0.5f * x), 0.5f, 0.5f);
}

__device__ __forceinline__ uint2 split_h2(float x, float y)
{
    __half2 hi = __floats2half2_rn(x, y);
    float2 hf = __half22float2(hi);
    __half2 lo = __floats2half2_rn(x - hf.x, y - hf.y);
    uint2 r;
    r.x = *(uint32_t*)&hi;
    r.y = *(uint32_t*)&lo;
    return r;
}

__device__ __forceinline__ void mbar_init(uint32_t addr, uint32_t count)
{
    asm volatile("mbarrier.init.shared.b64 [%0], %1;" :: "r"(addr), "r"(count)
                 : "memory");
}
__device__ __forceinline__ void mbar_expect_tx(uint32_t addr, uint32_t bytes)
{
    asm volatile("mbarrier.arrive.expect_tx.shared.b64 _, [%0], %1;"
                 :: "r"(addr), "r"(bytes) : "memory");
}
__device__ __forceinline__ void mbar_wait(uint32_t addr, uint32_t parity)
{
    asm volatile(
        "{\n\t"
        ".reg .pred P;\n\t"
        "LW%=:\n\t"
        "mbarrier.try_wait.parity.acquire.cta.shared::cta.b64 P, [%0], %1;\n\t"
        "@P bra LD%=;\n\t"
        "bra LW%=;\n\t"
        "LD%=:\n\t"
        "}"
        :: "r"(addr), "r"(parity) : "memory");
}

__device__ __forceinline__ void cp16(uint32_t dst, const void* src)
{
    asm volatile("cp.async.cg.shared.global [%0], [%1], 16;"
                 :: "r"(dst), "l"(src) : "memory");
}
__device__ __forceinline__ void cp_commit()
{
    asm volatile("cp.async.commit_group;" ::: "memory");
}

// ---------------------------------------------------------------------------
// Pre-split: fp32 -> (hi fp16, lo fp16) packed as uint2 per fp32-pair.
// ---------------------------------------------------------------------------
__global__ void presplit(const float4* __restrict__ in, uint4* __restrict__ out,
                         int n4)
{
    for (int i = blockIdx.x * blockDim.x + threadIdx.x; i < n4;
         i += gridDim.x * blockDim.x) {
        float4 v = in[i];
        uint2 a = split_h2(v.x, v.y);
        uint2 b = split_h2(v.z, v.w);
        out[i] = make_uint4(a.x, a.y, b.x, b.y);
    }
}

// ---------------------------------------------------------------------------
// 3-term fp16 split GEMM (NT), PRE-SPLIT operands, 2-stage cp.async pipeline
// (R11 measured-best version, byte-for-byte).
// ---------------------------------------------------------------------------
#define MMA_F16(d, a0, a1, a2, a3, b0, b1)                                    \
    asm("mma.sync.aligned.m16n8k16.row.col.f32.f16.f16.f32 "                   \
        "{%0,%1,%2,%3},{%4,%5,%6,%7},{%8,%9},{%0,%1,%2,%3};"                   \
        : "+f"((d)[0]), "+f"((d)[1]), "+f"((d)[2]), "+f"((d)[3])               \
        : "r"(a0), "r"(a1), "r"(a2), "r"(a3), "r"(b0), "r"(b1))

#define HPAD 10   // uint2 row stride (8 kpairs + 2 pad)

__global__ void __launch_bounds__(256, 2)
hgemm_pre(const uint2* __restrict__ Ah, const uint2* __restrict__ Bh,
          const float* __restrict__ bias1, const float* __restrict__ bias2,
          float* __restrict__ C, int K2, int N)
{
    __shared__ uint2 As[2][128][HPAD];
    __shared__ uint2 Bs[2][128][HPAD];

    const int tid  = threadIdx.x;
    const int lane = tid & 31;
    const int warp = tid >> 5;
    const int wm = warp & 1;
    const int wn = warp >> 1;
    const int g  = lane >> 2;
    const int t  = lane & 3;

    const size_t m0 = (size_t)blockIdx.x * 128;
    const int    n0 = blockIdx.y * 128;

    const int frow = tid >> 1;
    const int fc2  = (tid & 1) * 4;
    const uint2* Ag = Ah + (m0 + frow) * (size_t)K2 + fc2;
    const uint2* Bg = Bh + (size_t)(n0 + frow) * K2 + fc2;

    const uint32_t sA0 = (uint32_t)__cvta_generic_to_shared(&As[0][frow][fc2]);
    const uint32_t sA1 = (uint32_t)__cvta_generic_to_shared(&As[1][frow][fc2]);
    const uint32_t sB0 = (uint32_t)__cvta_generic_to_shared(&Bs[0][frow][fc2]);
    const uint32_t sB1 = (uint32_t)__cvta_generic_to_shared(&Bs[1][frow][fc2]);

    const int nblk = K2 >> 3;

    cp16(sA0, Ag);          cp16(sA0 + 16, Ag + 2);
    cp16(sB0, Bg);          cp16(sB0 + 16, Bg + 2);
    cp_commit();
    cp16(sA1, Ag + 8);      cp16(sA1 + 16, Ag + 10);
    cp16(sB1, Bg + 8);      cp16(sB1 + 16, Bg + 10);
    cp_commit();

    float acc[4][4][4];
#pragma unroll
    for (int i = 0; i < 4; ++i)
#pragma unroll
        for (int j = 0; j < 4; ++j)
#pragma unroll
            for (int q = 0; q < 4; ++q) acc[i][j][q] = 0.f;

    for (int kb = 0; kb < nblk; ++kb) {
        if (kb == nblk - 1)
            asm volatile("cp.async.wait_group 0;" ::: "memory");
        else
            asm volatile("cp.async.wait_group 1;" ::: "memory");
        __syncthreads();

        const int s = kb & 1;
        uint32_t ah[4][4], al[4][4], bh[4][2], bl[4][2];
#pragma unroll
        for (int i = 0; i < 4; ++i) {
            const int row = wm * 64 + i * 16 + g;
            uint2 q00 = As[s][row][t];
            uint2 q10 = As[s][row + 8][t];
            uint2 q01 = As[s][row][t + 4];
            uint2 q11 = As[s][row + 8][t + 4];
            ah[i][0] = q00.x; ah[i][1] = q10.x; ah[i][2] = q01.x; ah[i][3] = q11.x;
            al[i][0] = q00.y; al[i][1] = q10.y; al[i][2] = q01.y; al[i][3] = q11.y;
        }
#pragma unroll
        for (int j = 0; j < 4; ++j) {
            const int n = wn * 32 + j * 8 + g;
            uint2 p0 = Bs[s][n][t];
            uint2 p1 = Bs[s][n][t + 4];
            bh[j][0] = p0.x; bh[j][1] = p1.x;
            bl[j][0] = p0.y; bl[j][1] = p1.y;
        }
#pragma unroll
        for (int i = 0; i < 4; ++i)
#pragma unroll
            for (int j = 0; j < 4; ++j) {
                MMA_F16(acc[i][j], ah[i][0], ah[i][1], ah[i][2], ah[i][3],
                        bh[j][0], bh[j][1]);
                MMA_F16(acc[i][j], ah[i][0], ah[i][1], ah[i][2], ah[i][3],
                        bl[j][0], bl[j][1]);
                MMA_F16(acc[i][j], al[i][0], al[i][1], al[i][2], al[i][3],
                        bh[j][0], bh[j][1]);
            }
        __syncthreads();

        if (kb + 2 < nblk) {
            const int koff = (kb + 2) * 8;
            cp16(s ? sA1 : sA0, Ag + koff);
            cp16((s ? sA1 : sA0) + 16, Ag + koff + 2);
            cp16(s ? sB1 : sB0, Bg + koff);
            cp16((s ? sB1 : sB0) + 16, Bg + koff + 2);
            cp_commit();
        }
    }

#pragma unroll
    for (int j = 0; j < 4; ++j) {
        int col = n0 + wn * 32 + j * 8 + 2 * t;
        float b0 = bias1[col], b1 = bias1[col + 1];
        if (bias2) { b0 += bias2[col]; b1 += bias2[col + 1]; }
#pragma unroll
        for (int i = 0; i < 4; ++i) {
            size_t row = m0 + wm * 64 + i * 16 + g;
            *(float2*)(C + row * N + col) =
                make_float2(acc[i][j][0] + b0, acc[i][j][1] + b1);
            *(float2*)(C + (row + 8) * N + col) =
                make_float2(acc[i][j][2] + b0, acc[i][j][3] + b1);
        }
    }
}

// ---------------------------------------------------------------------------
// LSTM recurrence v9: R11/R10 structure (two-group pipeline, __syncthreads,
// per-(g,slot,rank) mbarriers) + two reducer-tail cuts:
//  (a) tanh.approx.f32 gates (accuracy validated in R14: rel_err 6.2e-6)
//  (b) shfl-coalesced scatter: 3 warp shuffles gather 4 lane-adjacent h;
//      lanes with jj%4==0 issue 8x st.async.v4 (16B) -> 128 msgs/step/CTA
//      instead of 512 4B msgs. Same 256B per-barrier expect_tx; protocol
//      unchanged. No extra synchronization (unlike R7's staging sync).
// ---------------------------------------------------------------------------
__global__ void __launch_bounds__(256, 1)
lstm_rec_kernel(const float* __restrict__ Whh,
                const float* __restrict__ Xp,
                uint2* __restrict__ hs_h)
{
    __shared__ float  hsm[2][3][8][64];        // [g][slot][rank][bb*32+jj]
    __shared__ float4 part[2][8][2][32];       // [g][warp][bb][jj] = 4 gates
    __shared__ __align__(8) unsigned long long mbar[48];  // [g][slot][rank]

    const int tid  = threadIdx.x;
    const int lane = tid & 31;
    const int w    = tid >> 5;

    unsigned r;
    asm("mov.u32 %0, %%cluster_ctarank;" : "=r"(r));
    const int cl = blockIdx.x >> 3;

    const uint32_t hsm_s = (uint32_t)__cvta_generic_to_shared(hsm);
    const uint32_t mb_s  = (uint32_t)__cvta_generic_to_shared(mbar);

    uint32_t pd[8], pm[8];
#pragma unroll
    for (int dst = 0; dst < 8; ++dst) {
        asm("mapa.shared::cluster.u32 %0, %1, %2;"
            : "=r"(pd[dst]) : "r"(hsm_s), "r"(dst));
        asm("mapa.shared::cluster.u32 %0, %1, %2;"
            : "=r"(pm[dst]) : "r"(mb_s), "r"(dst));
    }

    float2 wreg[4][16];
#pragma unroll
    for (int rr = 0; rr < 4; ++rr) {
        int grow = rr * 256 + (int)r * 32 + lane;
        const float2* wp = (const float2*)(Whh + (size_t)grow * 256 + w * 32);
#pragma unroll
        for (int k2 = 0; k2 < 16; ++k2) wreg[rr][k2] = wp[k2];
    }
    for (int i = tid; i < 2 * 3 * 8 * 64; i += 256) ((float*)hsm)[i] = 0.f;
    if (tid < 48) mbar_init(mb_s + tid * 8, 1);
    __syncthreads();
    if (tid < 48) mbar_expect_tx(mb_s + tid * 8, 256u);
    asm volatile("barrier.cluster.arrive.aligned;" ::: "memory");
    asm volatile("barrier.cluster.wait.aligned;"   ::: "memory");

    const int mg = tid >> 6;           // reducer group (tid<128)
    const int tl = tid & 63;
    const int bb = tl >> 5;
    const int jj = tl & 31;
    float c = 0.f;
    int par = 0;
    int rs = 0;

    const float* xp_base = Xp + ((size_t)cl * 4 + mg * 2 + bb) * 1024
                              + (int)r * 32 + jj;
    float xc0 = 0.f, xc1 = 0.f, xc2 = 0.f, xc3 = 0.f;
    if (tid < 128) {
        xc0 = xp_base[0]; xc1 = xp_base[256];
        xc2 = xp_base[512]; xc3 = xp_base[768];
    }

    for (int t = 0; t < T_STEPS; ++t) {
        const int ws = (rs == 2) ? 0 : rs + 1;

        // ============ group A ============
        if (t > 0)
            mbar_wait(mb_s + ((0 * 3 + rs) * 8 + w) * 8, (par >> rs) & 1);

        float xn0 = 0.f, xn1 = 0.f, xn2 = 0.f, xn3 = 0.f;
        if (tid < 128 && t + 1 < T_STEPS) {
            const float* xp = xp_base + (size_t)(t + 1) * 64 * 1024;
            xn0 = xp[0]; xn1 = xp[256]; xn2 = xp[512]; xn3 = xp[768];
        }

        {
            float2 acc[4][2];
#pragma unroll
            for (int rr = 0; rr < 4; ++rr) {
                acc[rr][0] = make_float2(0.f, 0.f);
                acc[rr][1] = make_float2(0.f, 0.f);
            }
            const float* hb = &hsm[0][rs][w][0];
#pragma unroll
            for (int k2 = 0; k2 < 16; ++k2) {
                float2 h0 = *(const float2*)(hb + 2 * k2);
                float2 h1 = *(const float2*)(hb + 32 + 2 * k2);
#pragma unroll
                for (int rr = 0; rr < 4; ++rr) {
                    ffma2(acc[rr][0], wreg[rr][k2], h0);
                    ffma2(acc[rr][1], wreg[rr][k2], h1);
                }
            }
#pragma unroll
            for (int b = 0; b < 2; ++b)
                part[0][w][b][lane] = make_float4(acc[0][b].x + acc[0][b].y,
                                                  acc[1][b].x + acc[1][b].y,
                                                  acc[2][b].x + acc[2][b].y,
                                                  acc[3][b].x + acc[3][b].y);
        }
        __syncthreads();
        if (t > 0 && tid < 8)
            mbar_expect_tx(mb_s + ((0 * 3 + rs) * 8 + tid) * 8, 256u);

        if (tid < 64) {
            float s0 = xc0, s1 = xc1, s2 = xc2, s3 = xc3;
#pragma unroll
            for (int w8 = 0; w8 < 8; ++w8) {
                float4 p = part[0][w8][bb][jj];
                s0 += p.x; s1 += p.y; s2 += p.z; s3 += p.w;
            }
            float ig = sig_ap(s0);
            float fg = sig_ap(s1);
            float gg = tanh_ap(s2);
            float og = sig_ap(s3);
            c = fg * c + ig * gg;
            float h = og * tanh_ap(c);

            // shfl-coalesced scatter: gather 4 lane-adjacent h, send v4.
            float v1 = __shfl_down_sync(0xFFFFFFFFu, h, 1);
            float v2 = __shfl_down_sync(0xFFFFFFFFu, h, 2);
            float v3 = __shfl_down_sync(0xFFFFFFFFu, h, 3);
            if (t < T_STEPS - 1 && (jj & 3) == 0) {
                uint32_t doff = (uint32_t)(0 * 6144 + ws * 2048 + (int)r * 256
                                           + tl * 4);
                uint32_t moff = (uint32_t)(((0 * 3 + ws) * 8 + (int)r) * 8);
#pragma unroll
                for (int dst = 0; dst < 8; ++dst)
                    asm volatile(
                        "st.async.shared::cluster.mbarrier::complete_tx::bytes"
                        ".v4.f32 [%0], {%1,%2,%3,%4}, [%5];"
                        :: "r"(pd[dst] + doff), "f"(h), "f"(v1), "f"(v2),
                           "f"(v3), "r"(pm[dst] + moff)
                        : "memory");
            }
            if (!(jj & 1)) {
                uint2 sv = split_h2(h, v1);
                hs_h[((size_t)t * 64 + cl * 4 + bb) * 128
                     + (int)r * 16 + (jj >> 1)] = sv;
            }
        }

        // ============ group B ============
        if (t > 0)
            mbar_wait(mb_s + ((1 * 3 + rs) * 8 + w) * 8, (par >> rs) & 1);

        {
            float2 acc[4][2];
#pragma unroll
            for (int rr = 0; rr < 4; ++rr) {
                acc[rr][0] = make_float2(0.f, 0.f);
                acc[rr][1] = make_float2(0.f, 0.f);
            }
            const float* hb = &hsm[1][rs][w][0];
#pragma unroll
            for (int k2 = 0; k2 < 16; ++k2) {
                float2 h0 = *(const float2*)(hb + 2 * k2);
                float2 h1 = *(const float2*)(hb + 32 + 2 * k2);
#pragma unroll
                for (int rr = 0; rr < 4; ++rr) {
                    ffma2(acc[rr][0], wreg[rr][k2], h0);
                    ffma2(acc[rr][1], wreg[rr][k2], h1);
                }
            }
#pragma unroll
            for (int b = 0; b < 2; ++b)
                part[1][w][b][lane] = make_float4(acc[0][b].x + acc[0][b].y,
                                                  acc[1][b].x + acc[1][b].y,
                                                  acc[2][b].x + acc[2][b].y,
                                                  acc[3][b].x + acc[3][b].y);
        }
        __syncthreads();
        if (t > 0 && tid < 8)
            mbar_expect_tx(mb_s + ((1 * 3 + rs) * 8 + tid) * 8, 256u);

        if (tid >= 64 && tid < 128) {
            float s0 = xc0, s1 = xc1, s2 = xc2, s3 = xc3;
#pragma unroll
            for (int w8 = 0; w8 < 8; ++w8) {
                float4 p = part[1][w8][bb][jj];
                s0 += p.x; s1 += p.y; s2 += p.z; s3 += p.w;
            }
            float ig = sig_ap(s0);
            float fg = sig_ap(s1);
            float gg = tanh_ap(s2);
            float og = sig_ap(s3);
            c = fg * c + ig * gg;
            float h = og * tanh_ap(c);

            float v1 = __shfl_down_sync(0xFFFFFFFFu, h, 1);
            float v2 = __shfl_down_sync(0xFFFFFFFFu, h, 2);
            float v3 = __shfl_down_sync(0xFFFFFFFFu, h, 3);
            if (t < T_STEPS - 1 && (jj & 3) == 0) {
                uint32_t doff = (uint32_t)(1 * 6144 + ws * 2048 + (int)r * 256
                                           + tl * 4);
                uint32_t moff = (uint32_t)(((1 * 3 + ws) * 8 + (int)r) * 8);
#pragma unroll
                for (int dst = 0; dst < 8; ++dst)
                    asm volatile(
                        "st.async.shared::cluster.mbarrier::complete_tx::bytes"
                        ".v4.f32 [%0], {%1,%2,%3,%4}, [%5];"
                        :: "r"(pd[dst] + doff), "f"(h), "f"(v1), "f"(v2),
                           "f"(v3), "r"(pm[dst] + moff)
                        : "memory");
            }
            if (!(jj & 1)) {
                uint2 sv = split_h2(h, v1);
                hs_h[((size_t)t * 64 + cl * 4 + 2 + bb) * 128
                     + (int)r * 16 + (jj >> 1)] = sv;
            }
        }

        xc0 = xn0; xc1 = xn1; xc2 = xn2; xc3 = xn3;
        if (t > 0) par ^= (1 << rs);
        rs = ws;
    }

    asm volatile("barrier.cluster.arrive.aligned;" ::: "memory");
    asm volatile("barrier.cluster.wait.aligned;"   ::: "memory");
}

// ---------------------------------------------------------------------------
// Launch
// ---------------------------------------------------------------------------
extern "C" void kernel_launch(void* const* d_in, const int* in_sizes, int n_in,
                              void* d_out, int out_size)
{
    const float* inputs = (const float*)d_in[0];
    const float* W_ih   = (const float*)d_in[1];
    const float* W_hh   = (const float*)d_in[2];
    const float* b_ih   = (const float*)d_in[3];
    const float* b_hh   = (const float*)d_in[4];
    const float* W_fc   = (const float*)d_in[5];
    const float* b_fc   = (const float*)d_in[6];
    float* out = (float*)d_out;

    float *Xp;
    uint4 *Ah, *Wih, *hsh, *Wfc;
    cudaGetSymbolAddress((void**)&Xp,  g_Xp);
    cudaGetSymbolAddress((void**)&Ah,  g_Ah);
    cudaGetSymbolAddress((void**)&Wih, g_Wih);
    cudaGetSymbolAddress((void**)&hsh, g_hsh);
    cudaGetSymbolAddress((void**)&Wfc, g_Wfc);

    // 0) Pre-split fp32 -> fp16 hi/lo pairs.
    presplit<<<4096, 256>>>((const float4*)inputs, Ah, MROWS * INSZ / 4);
    presplit<<<512, 256>>>((const float4*)W_ih, Wih, G4 * INSZ / 4);
    presplit<<<32, 256>>>((const float4*)W_fc, Wfc, OUTSZ * HID / 4);

    // 1) Xp = inputs @ W_ih^T + (b_ih + b_hh)   [131072 x 1024]
    {
        dim3 grid(MROWS / 128, G4 / 128);
        hgemm_pre<<<grid, 256>>>((const uint2*)Ah, (const uint2*)Wih,
                                 b_ih, b_hh, Xp, INSZ / 2, G4);
    }

    // 2) LSTM recurrence -> hs (pre-split) [131072 x 256]
    {
        cudaLaunchConfig_t cfg = {};
        cfg.gridDim = dim3(128, 1, 1);
        cfg.blockDim = dim3(256, 1, 1);
        cfg.dynamicSmemBytes = 0;
        cfg.stream = 0;
        cudaLaunchAttribute attr[1];
        attr[0].id = cudaLaunchAttributeClusterDimension;
        attr[0].val.clusterDim.x = 8;
        attr[0].val.clusterDim.y = 1;
        attr[0].val.clusterDim.z = 1;
        cfg.attrs = attr;
        cfg.numAttrs = 1;
        cudaLaunchKernelEx(&cfg, lstm_rec_kernel, W_hh, (const float*)Xp,
                           (uint2*)hsh);
    }

    // 3) out = hs @ W_fc^T + b_fc   [131072 x 128]
    {
        dim3 grid(MROWS / 128, OUTSZ / 128);
        hgemm_pre<<<grid, 256>>>((const uint2*)hsh, (const uint2*)Wfc,
                                 b_fc, (const float*)nullptr, out,
                                 HID / 2, OUTSZ);
    }
}